// round 10
// baseline (speedup 1.0000x reference)
#include <cuda_runtime.h>
#include <cstdint>

#define DIM   128
#define LMAX  20
#define NBKT  256          // 2MB pages: idx>>12 (4096 rows/page), 1M rows -> 245 used
#define CAP   256          // max elems/bucket (mean 67, +7sigma ~ 130)
#define MAXB  16384
#define NCTA  512

__device__ int          g_hist[2][NBKT];
__device__ int2         g_slots[2][NBKT * CAP];   // (elem, row_index)
__device__ float        g_scratch[MAXB * DIM];    // W0 rows by element (8MB, L2-resident)
__device__ float        g_loss[MAXB];
__device__ unsigned int g_bar[3];                 // barrier A, barrier B, completion

__device__ __forceinline__ void grid_barrier(unsigned int* cnt) {
    __syncthreads();
    if (threadIdx.x == 0) {
        __threadfence();
        const unsigned int arrived = atomicAdd(cnt, 1u) + 1u;
        if (arrived < NCTA) {
            while (*((volatile unsigned int*)cnt) < NCTA) __nanosleep(40);
        }
        __threadfence();
    }
    __syncthreads();
}

__global__ void __launch_bounds__(256, 4) sg_fused_kernel(
    const float* __restrict__ W0,
    const float* __restrict__ W1,
    const int* __restrict__ target,
    const int* __restrict__ context,
    const int* __restrict__ codes,
    const int* __restrict__ lengths,
    float* __restrict__ out,
    int B, int n_nodes)
{
    const int lane = threadIdx.x & 31;
    const int wid  = threadIdx.x >> 5;

    // ---------- phase A: bin every element by 2MB page of each index ----------
    {
        const int i = blockIdx.x * 256 + threadIdx.x;   // NCTA*256 >= B
        if (i < B) {
            int t = target[i];  if ((unsigned)t >= (unsigned)n_nodes) t = 0;
            int c = context[i]; if ((unsigned)c >= (unsigned)n_nodes) c = 0;
            const int b0 = (t >> 12) & (NBKT - 1);
            const int p0 = atomicAdd(&g_hist[0][b0], 1);
            if (p0 < CAP) g_slots[0][b0 * CAP + p0] = make_int2(i, t);
            const int b1 = (c >> 12) & (NBKT - 1);
            const int p1 = atomicAdd(&g_hist[1][b1], 1);
            if (p1 < CAP) g_slots[1][b1 * CAP + p1] = make_int2(i, c);
        }
    }
    grid_barrier(&g_bar[0]);

    // ---------- phase B: page-local gather of W0 rows -> scratch ----------
    // 2 CTAs per bucket, 16 warps/bucket; each CTA touches ~one 2MB page.
    {
        const int bkt = blockIdx.x >> 1;
        const int gw  = ((blockIdx.x & 1) << 3) + wid;          // 0..15
        int n = __ldcg(&g_hist[0][bkt]); if (n > CAP) n = CAP;
        for (int k0 = gw * 4; k0 < n; k0 += 64) {
            const int m = min(4, n - k0);
            int2 s[4]; float4 v[4];
            #pragma unroll
            for (int u = 0; u < 4; ++u)
                if (u < m) s[u] = __ldcg(&g_slots[0][bkt * CAP + k0 + u]);
            #pragma unroll
            for (int u = 0; u < 4; ++u)
                if (u < m) v[u] = reinterpret_cast<const float4*>(W0 + (long long)s[u].y * DIM)[lane];
            #pragma unroll
            for (int u = 0; u < 4; ++u)
                if (u < m) reinterpret_cast<float4*>(g_scratch + s[u].x * DIM)[lane] = v[u];
        }
    }
    grid_barrier(&g_bar[1]);

    // ---------- phase C: page-local gather of W1 + per-element loss ----------
    {
        const int bkt = blockIdx.x >> 1;
        const int gw  = ((blockIdx.x & 1) << 3) + wid;
        int n = __ldcg(&g_hist[1][bkt]); if (n > CAP) n = CAP;
        for (int k0 = gw * 2; k0 < n; k0 += 32) {
            const int m = min(2, n - k0);
            int2 s[2]; float4 a[2], b[2]; int len[2], code[2];
            #pragma unroll
            for (int u = 0; u < 2; ++u)
                if (u < m) s[u] = __ldcg(&g_slots[1][bkt * CAP + k0 + u]);
            #pragma unroll
            for (int u = 0; u < 2; ++u) {
                if (u < m) {
                    b[u]    = reinterpret_cast<const float4*>(W1 + (long long)s[u].y * DIM)[lane];
                    a[u]    = __ldcg(reinterpret_cast<const float4*>(g_scratch + s[u].x * DIM) + lane);
                    len[u]  = lengths[s[u].x];
                    code[u] = (lane < LMAX) ? codes[s[u].x * LMAX + lane] : 0;
                }
            }
            #pragma unroll
            for (int u = 0; u < 2; ++u) {
                if (u < m) {
                    float dot = a[u].x * b[u].x + a[u].y * b[u].y
                              + a[u].z * b[u].z + a[u].w * b[u].w;
                    #pragma unroll
                    for (int o = 16; o > 0; o >>= 1)
                        dot += __shfl_xor_sync(0xffffffffu, dot, o);
                    float v = 0.0f;
                    if (lane < len[u]) {
                        const float sign = 1.0f - 2.0f * (float)code[u];
                        const float x = sign * dot;
                        // stable log_sigmoid: min(x,0) - log1p(exp(-|x|))
                        v = -(fminf(x, 0.0f) - log1pf(__expf(-fabsf(x))));
                    }
                    #pragma unroll
                    for (int o = 16; o > 0; o >>= 1)
                        v += __shfl_xor_sync(0xffffffffu, v, o);
                    if (lane == 0) g_loss[s[u].x] = v;  // value is schedule-independent
                }
            }
        }
    }

    // ---------- completion: last CTA does fixed-order reduce + state reset ----------
    __shared__ bool is_last;
    __syncthreads();
    if (threadIdx.x == 0) {
        __threadfence();
        is_last = (atomicAdd(&g_bar[2], 1u) == NCTA - 1);
    }
    __syncthreads();

    if (is_last) {
        __threadfence();
        float sloc = 0.0f;
        #pragma unroll 4
        for (int i = threadIdx.x; i < B; i += 256)      // fixed order per thread
            sloc += __ldcg(&g_loss[i]);
        #pragma unroll
        for (int o = 16; o > 0; o >>= 1)
            sloc += __shfl_xor_sync(0xffffffffu, sloc, o);
        __shared__ float smem[8];
        if (lane == 0) smem[wid] = sloc;
        __syncthreads();
        if (threadIdx.x == 0) {
            float s = 0.0f;
            #pragma unroll
            for (int i = 0; i < 8; ++i) s += smem[i];
            out[0] = s;
            g_bar[0] = 0; g_bar[1] = 0; g_bar[2] = 0;   // reset for next replay
        }
        g_hist[0][threadIdx.x] = 0;                      // 256 threads cover NBKT
        g_hist[1][threadIdx.x] = 0;
    }
}

extern "C" void kernel_launch(void* const* d_in, const int* in_sizes, int n_in,
                              void* d_out, int out_size)
{
    const float* W0      = (const float*)d_in[0];
    const float* W1      = (const float*)d_in[1];
    const int*   target  = (const int*)d_in[2];
    const int*   context = (const int*)d_in[3];
    const int*   codes   = (const int*)d_in[4];
    const int*   lengths = (const int*)d_in[5];
    float* out = (float*)d_out;

    int B = in_sizes[2];                       // 16384
    if (B > MAXB) B = MAXB;
    const int n_nodes = in_sizes[0] / DIM;     // 1,000,000

    sg_fused_kernel<<<NCTA, 256>>>(W0, W1, target, context, codes, lengths, out, B, n_nodes);
}

// round 11
// speedup vs baseline: 2.4884x; 2.4884x over previous
#include <cuda_runtime.h>

#define DIM   128
#define LMAX  20
#define EPW   2      // elements per warp
#define WPB   8      // warps per block -> 16 elements per CTA
#define MAXCTA 2048

__device__ float        g_partials[MAXCTA];
__device__ unsigned int g_counter = 0;

__global__ void __launch_bounds__(256) sg_loss_kernel(
    const float* __restrict__ W0,
    const float* __restrict__ W1,
    const int* __restrict__ target,
    const int* __restrict__ context,
    const int* __restrict__ codes,
    const int* __restrict__ lengths,
    float* __restrict__ out,
    int B, int n_nodes)
{
    const int lane = threadIdx.x & 31;
    const int wid  = threadIdx.x >> 5;
    const int base = (blockIdx.x * WPB + wid) * EPW;

    float acc = 0.0f;

    if (base < B) {
        // ---- hoist ALL small loads: indices, lengths, codes (independent misses) ----
        int t[EPW], c[EPW], len[EPW], code[EPW];
        #pragma unroll
        for (int e = 0; e < EPW; ++e) {
            const int i = base + e;
            const bool inb = (i < B);
            t[e]    = inb ? target[i]  : 0;
            c[e]    = inb ? context[i] : 0;
            len[e]  = inb ? lengths[i] : 0;
            code[e] = (inb && lane < LMAX) ? codes[i * LMAX + lane] : 0;
        }

        // ---- 4 row gathers back-to-back ----
        float4 a[EPW], b[EPW];
        #pragma unroll
        for (int e = 0; e < EPW; ++e) {
            const bool ok = (base + e < B) &&
                            (unsigned)t[e] < (unsigned)n_nodes &&
                            (unsigned)c[e] < (unsigned)n_nodes;
            const long long ti = ok ? (long long)t[e] : 0;
            const long long ci = ok ? (long long)c[e] : 0;
            a[e] = reinterpret_cast<const float4*>(W0 + ti * DIM)[lane];
            b[e] = reinterpret_cast<const float4*>(W1 + ci * DIM)[lane];
            if (!ok) len[e] = 0;
        }

        // ---- dot + log-sigmoid levels ----
        #pragma unroll
        for (int e = 0; e < EPW; ++e) {
            float dot = a[e].x * b[e].x + a[e].y * b[e].y
                      + a[e].z * b[e].z + a[e].w * b[e].w;
            #pragma unroll
            for (int o = 16; o > 0; o >>= 1)
                dot += __shfl_xor_sync(0xffffffffu, dot, o);
            if (lane < len[e]) {
                const float sign = 1.0f - 2.0f * (float)code[e];
                const float x = sign * dot;
                // stable log_sigmoid: min(x,0) - log1p(exp(-|x|))
                acc -= fminf(x, 0.0f) - log1pf(__expf(-fabsf(x)));
            }
        }
    }

    // ---- warp + block reduce (no global atomic adds to the result) ----
    #pragma unroll
    for (int o = 16; o > 0; o >>= 1)
        acc += __shfl_xor_sync(0xffffffffu, acc, o);

    __shared__ float smem[WPB];
    __shared__ bool  is_last;
    if (lane == 0) smem[wid] = acc;
    __syncthreads();
    if (threadIdx.x == 0) {
        float s = 0.0f;
        #pragma unroll
        for (int i = 0; i < WPB; ++i) s += smem[i];
        g_partials[blockIdx.x] = s;
        __threadfence();
        is_last = (atomicAdd(&g_counter, 1u) == gridDim.x - 1);
    }
    __syncthreads();

    // ---- last CTA: fixed-order final reduce (deterministic) ----
    if (is_last) {
        __threadfence();
        const int nb = gridDim.x;
        float v = 0.0f;
        for (int i = threadIdx.x; i < nb; i += blockDim.x)
            v += g_partials[i];
        #pragma unroll
        for (int o = 16; o > 0; o >>= 1)
            v += __shfl_xor_sync(0xffffffffu, v, o);
        __shared__ float smem2[WPB];
        if (lane == 0) smem2[wid] = v;
        __syncthreads();
        if (threadIdx.x == 0) {
            float s = 0.0f;
            #pragma unroll
            for (int i = 0; i < WPB; ++i) s += smem2[i];
            out[0] = s;
            g_counter = 0;   // reset for next graph replay
        }
    }
}

extern "C" void kernel_launch(void* const* d_in, const int* in_sizes, int n_in,
                              void* d_out, int out_size)
{
    const float* W0      = (const float*)d_in[0];
    const float* W1      = (const float*)d_in[1];
    const int*   target  = (const int*)d_in[2];
    const int*   context = (const int*)d_in[3];
    const int*   codes   = (const int*)d_in[4];
    const int*   lengths = (const int*)d_in[5];
    float* out = (float*)d_out;

    const int B = in_sizes[2];                 // 16384
    const int n_nodes = in_sizes[0] / DIM;     // 1,000,000
    const int epc = WPB * EPW;                 // 16 elements per CTA
    int blocks = (B + epc - 1) / epc;          // 1024
    if (blocks > MAXCTA) blocks = MAXCTA;

    sg_loss_kernel<<<blocks, 256>>>(W0, W1, target, context, codes, lengths, out, B, n_nodes);
}

// round 12
// speedup vs baseline: 2.5861x; 1.0393x over previous
#include <cuda_runtime.h>

#define DIM   128
#define LMAX  20
#define EPW   2      // elements per warp
#define WPB   8      // warps per block -> 16 elements per CTA
#define MAXCTA 2048

__device__ float        g_partials[MAXCTA];
__device__ unsigned int g_counter = 0;

// float4 global load with 256B L2 fetch-granule hint (halves miss-transaction count)
__device__ __forceinline__ float4 ldg_256b(const float4* p) {
    float4 v;
    asm volatile("ld.global.nc.L2::256B.v4.f32 {%0,%1,%2,%3}, [%4];"
                 : "=f"(v.x), "=f"(v.y), "=f"(v.z), "=f"(v.w)
                 : "l"(p));
    return v;
}

__global__ void __launch_bounds__(256) sg_loss_kernel(
    const float* __restrict__ W0,
    const float* __restrict__ W1,
    const int* __restrict__ target,
    const int* __restrict__ context,
    const int* __restrict__ codes,
    const int* __restrict__ lengths,
    float* __restrict__ out,
    int B, int n_nodes)
{
    const int lane = threadIdx.x & 31;
    const int wid  = threadIdx.x >> 5;
    const int base = (blockIdx.x * WPB + wid) * EPW;

    float acc = 0.0f;

    if (base < B) {
        // ---- hoist ALL small loads: indices, lengths, codes ----
        int t[EPW], c[EPW], len[EPW], code[EPW];
        #pragma unroll
        for (int e = 0; e < EPW; ++e) {
            const int i = base + e;
            const bool inb = (i < B);
            t[e]    = inb ? target[i]  : 0;
            c[e]    = inb ? context[i] : 0;
            len[e]  = inb ? lengths[i] : 0;
            code[e] = (inb && lane < LMAX) ? codes[i * LMAX + lane] : 0;
        }

        // ---- 4 row gathers back-to-back, 256B L2 granule ----
        float4 a[EPW], b[EPW];
        #pragma unroll
        for (int e = 0; e < EPW; ++e) {
            const bool ok = (base + e < B) &&
                            (unsigned)t[e] < (unsigned)n_nodes &&
                            (unsigned)c[e] < (unsigned)n_nodes;
            const long long ti = ok ? (long long)t[e] : 0;
            const long long ci = ok ? (long long)c[e] : 0;
            a[e] = ldg_256b(reinterpret_cast<const float4*>(W0 + ti * DIM) + lane);
            b[e] = ldg_256b(reinterpret_cast<const float4*>(W1 + ci * DIM) + lane);
            if (!ok) len[e] = 0;
        }

        // ---- dot + log-sigmoid levels ----
        #pragma unroll
        for (int e = 0; e < EPW; ++e) {
            float dot = a[e].x * b[e].x + a[e].y * b[e].y
                      + a[e].z * b[e].z + a[e].w * b[e].w;
            #pragma unroll
            for (int o = 16; o > 0; o >>= 1)
                dot += __shfl_xor_sync(0xffffffffu, dot, o);
            if (lane < len[e]) {
                const float sign = 1.0f - 2.0f * (float)code[e];
                const float x = sign * dot;
                // stable log_sigmoid: min(x,0) - log1p(exp(-|x|))
                acc -= fminf(x, 0.0f) - log1pf(__expf(-fabsf(x)));
            }
        }
    }

    // ---- warp + block reduce ----
    #pragma unroll
    for (int o = 16; o > 0; o >>= 1)
        acc += __shfl_xor_sync(0xffffffffu, acc, o);

    __shared__ float smem[WPB];
    __shared__ bool  is_last;
    if (lane == 0) smem[wid] = acc;
    __syncthreads();
    if (threadIdx.x == 0) {
        float s = 0.0f;
        #pragma unroll
        for (int i = 0; i < WPB; ++i) s += smem[i];
        g_partials[blockIdx.x] = s;
        __threadfence();
        is_last = (atomicAdd(&g_counter, 1u) == gridDim.x - 1);
    }
    __syncthreads();

    // ---- last CTA: fixed-order final reduce (deterministic) ----
    if (is_last) {
        __threadfence();
        const int nb = gridDim.x;
        float v = 0.0f;
        for (int i = threadIdx.x; i < nb; i += blockDim.x)
            v += g_partials[i];
        #pragma unroll
        for (int o = 16; o > 0; o >>= 1)
            v += __shfl_xor_sync(0xffffffffu, v, o);
        __shared__ float smem2[WPB];
        if (lane == 0) smem2[wid] = v;
        __syncthreads();
        if (threadIdx.x == 0) {
            float s = 0.0f;
            #pragma unroll
            for (int i = 0; i < WPB; ++i) s += smem2[i];
            out[0] = s;
            g_counter = 0;   // reset for next graph replay
        }
    }
}

extern "C" void kernel_launch(void* const* d_in, const int* in_sizes, int n_in,
                              void* d_out, int out_size)
{
    const float* W0      = (const float*)d_in[0];
    const float* W1      = (const float*)d_in[1];
    const int*   target  = (const int*)d_in[2];
    const int*   context = (const int*)d_in[3];
    const int*   codes   = (const int*)d_in[4];
    const int*   lengths = (const int*)d_in[5];
    float* out = (float*)d_out;

    const int B = in_sizes[2];                 // 16384
    const int n_nodes = in_sizes[0] / DIM;     // 1,000,000
    const int epc = WPB * EPW;                 // 16 elements per CTA
    int blocks = (B + epc - 1) / epc;          // 1024
    if (blocks > MAXCTA) blocks = MAXCTA;

    sg_loss_kernel<<<blocks, 256>>>(W0, W1, target, context, codes, lengths, out, B, n_nodes);
}